// round 1
// baseline (speedup 1.0000x reference)
#include <cuda_runtime.h>
#include <cuda_bf16.h>
#include <math.h>

// Problem constants
#define BATCH 1024
#define FDIM  128
#define EDIM  256
#define HEADS 8
#define DHEAD 32           // EDIM / HEADS
#define MROWS (BATCH * FDIM)   // 131072
#define NCOLS (4 * EDIM)       // 1024 : [Q | K | V | R]

// Scratch for Q|K|V|R projections: 131072 x 1024 fp32 = 536 MB
__device__ float g_qkvr[(size_t)MROWS * NCOLS];

// ---------------------------------------------------------------------------
// Kernel A: fused projection GEMM.  C[131072 x 1024] = A[131072 x 256] @ W
// where W columns 0..255 = W_Query, 256..511 = W_key, 512..767 = W_Value,
// 768..1023 = W_Res.  Classic 128x128x16 tile, 8x8 per thread, fp32.
// ---------------------------------------------------------------------------
#define GBM 128
#define GBN 128
#define GBK 16

__global__ __launch_bounds__(256, 2) void proj_gemm_kernel(
    const float* __restrict__ A,
    const float* __restrict__ Wq, const float* __restrict__ Wk,
    const float* __restrict__ Wv, const float* __restrict__ Wr)
{
    __shared__ float sA[GBK][GBM + 4];   // transposed A tile
    __shared__ float sB[GBK][GBN];

    const int tid = threadIdx.x;
    const int m0 = blockIdx.y * GBM;
    const int n0 = blockIdx.x * GBN;

    const float* W = (n0 < 256) ? Wq : (n0 < 512) ? Wk : (n0 < 768) ? Wv : Wr;
    const int wn0 = n0 & 255;

    const int tx = tid & 15;          // 0..15 -> N direction
    const int ty = tid >> 4;          // 0..15 -> M direction

    float acc[8][8];
#pragma unroll
    for (int i = 0; i < 8; i++)
#pragma unroll
        for (int j = 0; j < 8; j++) acc[i][j] = 0.f;

    for (int k0 = 0; k0 < EDIM; k0 += GBK) {
        // Load A tile: 128 rows x 16 cols = 512 float4, 2 per thread
#pragma unroll
        for (int s = 0; s < 2; s++) {
            int ar = (tid >> 2) + s * 64;       // 0..127
            int ac = (tid & 3) * 4;             // 0,4,8,12
            float4 v = *(const float4*)&A[(size_t)(m0 + ar) * EDIM + k0 + ac];
            sA[ac + 0][ar] = v.x;
            sA[ac + 1][ar] = v.y;
            sA[ac + 2][ar] = v.z;
            sA[ac + 3][ar] = v.w;
        }
        // Load W tile: 16 rows x 128 cols = 512 float4, 2 per thread
#pragma unroll
        for (int s = 0; s < 2; s++) {
            int br = tid >> 4;                      // 0..15
            int bc = ((tid & 15) + s * 16) * 4;     // 0..124
            float4 v = *(const float4*)&W[(size_t)(k0 + br) * EDIM + wn0 + bc];
            *(float4*)&sB[br][bc] = v;
        }
        __syncthreads();

#pragma unroll
        for (int kk = 0; kk < GBK; kk++) {
            float a[8], b[8];
#pragma unroll
            for (int i = 0; i < 8; i++) a[i] = sA[kk][ty * 8 + i];
#pragma unroll
            for (int j = 0; j < 8; j++) b[j] = sB[kk][tx * 8 + j];
#pragma unroll
            for (int i = 0; i < 8; i++)
#pragma unroll
                for (int j = 0; j < 8; j++)
                    acc[i][j] = fmaf(a[i], b[j], acc[i][j]);
        }
        __syncthreads();
    }

#pragma unroll
    for (int i = 0; i < 8; i++) {
        size_t row = (size_t)(m0 + ty * 8 + i);
#pragma unroll
        for (int j = 0; j < 8; j += 4) {
            float4 v = make_float4(acc[i][j], acc[i][j + 1], acc[i][j + 2], acc[i][j + 3]);
            *(float4*)&g_qkvr[row * NCOLS + n0 + tx * 8 + j] = v;
        }
    }
}

// ---------------------------------------------------------------------------
// Kernel B: attention per (b, h).  256 threads.
//   Q,K,V tiles 128x32 in smem (stride 36 to dodge bank conflicts),
//   S = Q K^T in registers (8x8 per thread over a 16x16 thread grid),
//   warp-shuffle row softmax (no scaling), normalized P staged in smem,
//   O = P V, epilogue adds residual projection and applies ReLU.
// Dynamic smem: 3*128*36 + 128*132 floats = 122880 B.
// ---------------------------------------------------------------------------
#define QSTRIDE 36
#define SSTRIDE 132
#define ATT_SMEM_FLOATS (3 * 128 * QSTRIDE + 128 * SSTRIDE)
#define ATT_SMEM_BYTES  (ATT_SMEM_FLOATS * 4)

__global__ __launch_bounds__(256, 1) void attn_kernel(float* __restrict__ out)
{
    extern __shared__ float smem[];
    float* sQ = smem;                      // 128 x 36
    float* sK = sQ + 128 * QSTRIDE;        // 128 x 36
    float* sV = sK + 128 * QSTRIDE;        // 128 x 36
    float* sS = sV + 128 * QSTRIDE;        // 128 x 132

    const int bh = blockIdx.x;
    const int b = bh >> 3;
    const int h = bh & 7;
    const int tid = threadIdx.x;

    const size_t rowbase = (size_t)(b * FDIM) * NCOLS;
    const int colQ = h * DHEAD;

    // Load Q, K, V tiles: 128 rows x 8 float4 each
#pragma unroll
    for (int s = 0; s < 4; s++) {
        int idx = tid + s * 256;           // 0..1023
        int r = idx >> 3;
        int c4 = (idx & 7) * 4;
        const float* src = &g_qkvr[rowbase + (size_t)r * NCOLS + colQ + c4];
        float4 q = *(const float4*)(src);
        float4 k = *(const float4*)(src + 256);
        float4 v = *(const float4*)(src + 512);
        *(float4*)&sQ[r * QSTRIDE + c4] = q;
        *(float4*)&sK[r * QSTRIDE + c4] = k;
        *(float4*)&sV[r * QSTRIDE + c4] = v;
    }
    __syncthreads();

    // ---- S = Q K^T ----
    const int tx = tid & 15;   // col tile (j)
    const int ty = tid >> 4;   // row tile (i)
    float acc[8][8];
#pragma unroll
    for (int i = 0; i < 8; i++)
#pragma unroll
        for (int j = 0; j < 8; j++) acc[i][j] = 0.f;

#pragma unroll
    for (int d4 = 0; d4 < DHEAD; d4 += 4) {
        float4 kv[8];
#pragma unroll
        for (int j = 0; j < 8; j++)
            kv[j] = *(const float4*)&sK[(tx * 8 + j) * QSTRIDE + d4];
#pragma unroll
        for (int i = 0; i < 8; i++) {
            float4 q = *(const float4*)&sQ[(ty * 8 + i) * QSTRIDE + d4];
#pragma unroll
            for (int j = 0; j < 8; j++) {
                acc[i][j] = fmaf(q.x, kv[j].x, acc[i][j]);
                acc[i][j] = fmaf(q.y, kv[j].y, acc[i][j]);
                acc[i][j] = fmaf(q.z, kv[j].z, acc[i][j]);
                acc[i][j] = fmaf(q.w, kv[j].w, acc[i][j]);
            }
        }
    }

    // ---- row softmax (no scaling), write normalized P to sS ----
#pragma unroll
    for (int i = 0; i < 8; i++) {
        float m = acc[i][0];
#pragma unroll
        for (int j = 1; j < 8; j++) m = fmaxf(m, acc[i][j]);
#pragma unroll
        for (int o = 8; o >= 1; o >>= 1)
            m = fmaxf(m, __shfl_xor_sync(0xffffffffu, m, o));
        float ssum = 0.f;
#pragma unroll
        for (int j = 0; j < 8; j++) {
            float p = __expf(acc[i][j] - m);
            acc[i][j] = p;
            ssum += p;
        }
#pragma unroll
        for (int o = 8; o >= 1; o >>= 1)
            ssum += __shfl_xor_sync(0xffffffffu, ssum, o);
        float inv = 1.0f / ssum;
#pragma unroll
        for (int j = 0; j < 8; j++)
            sS[(ty * 8 + i) * SSTRIDE + tx * 8 + j] = acc[i][j] * inv;
    }
    __syncthreads();

    // ---- O = P V ----  (thread -> 8 rows x 2 cols of the 128x32 output)
    const int dgrp = tid & 15;   // col pair: dgrp*2
    const int rgrp = tid >> 4;   // row group: rgrp*8
    float o0[8], o1[8];
#pragma unroll
    for (int i = 0; i < 8; i++) { o0[i] = 0.f; o1[i] = 0.f; }

#pragma unroll 4
    for (int j = 0; j < 128; j++) {
        float v0 = sV[j * QSTRIDE + dgrp * 2];
        float v1 = sV[j * QSTRIDE + dgrp * 2 + 1];
#pragma unroll
        for (int i = 0; i < 8; i++) {
            float p = sS[(rgrp * 8 + i) * SSTRIDE + j];
            o0[i] = fmaf(p, v0, o0[i]);
            o1[i] = fmaf(p, v1, o1[i]);
        }
    }

    // ---- epilogue: + residual projection, ReLU, store ----
    const size_t orowbase = (size_t)(b * FDIM);
#pragma unroll
    for (int i = 0; i < 8; i++) {
        int r = rgrp * 8 + i;
        const float2 rr = *(const float2*)&g_qkvr[rowbase + (size_t)r * NCOLS + 768 + colQ + dgrp * 2];
        float2 res;
        res.x = fmaxf(o0[i] + rr.x, 0.f);
        res.y = fmaxf(o1[i] + rr.y, 0.f);
        *(float2*)&out[(orowbase + r) * EDIM + colQ + dgrp * 2] = res;
    }
}

// ---------------------------------------------------------------------------
// Launch
// ---------------------------------------------------------------------------
extern "C" void kernel_launch(void* const* d_in, const int* in_sizes, int n_in,
                              void* d_out, int out_size)
{
    const float* inputs = (const float*)d_in[0];
    const float* Wq     = (const float*)d_in[1];
    const float* Wk     = (const float*)d_in[2];
    const float* Wv     = (const float*)d_in[3];
    const float* Wr     = (const float*)d_in[4];
    float* out = (float*)d_out;

    cudaFuncSetAttribute(attn_kernel, cudaFuncAttributeMaxDynamicSharedMemorySize,
                         ATT_SMEM_BYTES);

    dim3 gridA(NCOLS / GBN, MROWS / GBM);   // 8 x 1024
    proj_gemm_kernel<<<gridA, 256>>>(inputs, Wq, Wk, Wv, Wr);

    attn_kernel<<<BATCH * HEADS, 256, ATT_SMEM_BYTES>>>(out);
}

// round 3
// speedup vs baseline: 1.5576x; 1.5576x over previous
#include <cuda_runtime.h>
#include <cuda_bf16.h>
#include <cstdint>
#include <math.h>

// Problem constants
#define BATCH 1024
#define FDIM  128
#define EDIM  256
#define HEADS 8
#define DHEAD 32
#define MROWS (BATCH * FDIM)   // 131072
#define NCOLS (4 * EDIM)       // 1024 : [Q | K | V | R]

// ---------------------------------------------------------------------------
// Device scratch (no allocations allowed)
// ---------------------------------------------------------------------------
__device__ float g_qkvr[(size_t)MROWS * NCOLS];                 // 537 MB
__device__ __nv_bfloat16 g_Ahi[(size_t)MROWS * EDIM];           // 67 MB
__device__ __nv_bfloat16 g_Alo[(size_t)MROWS * EDIM];           // 67 MB
__device__ __nv_bfloat16 g_Bhi[(size_t)NCOLS * EDIM];           // [n][k] = W[k][n]
__device__ __nv_bfloat16 g_Blo[(size_t)NCOLS * EDIM];

// ---------------------------------------------------------------------------
// mma.sync m16n8k16 bf16 -> f32 (baseline PTX, works on compute_103)
// Thread mapping (row.col):
//   A (row-major m16 x k16): a0=(m=lane/4,     k=2*(lane%4)), a1=(m+8, k),
//                            a2=(m,  k+8),     a3=(m+8, k+8)   [each reg = k,k+1 pair]
//   B (col-major k16 x n8):  b0=(k=2*(lane%4), n=lane/4), b1=(k+8, n)
//   C: c0=(m=lane/4, n=2*(lane%4)), c1=(m, n+1), c2=(m+8, n), c3=(m+8, n+1)
// ---------------------------------------------------------------------------
__device__ __forceinline__ void mma16816(float* c, const uint32_t* a, const uint32_t* b) {
    asm volatile(
        "mma.sync.aligned.m16n8k16.row.col.f32.bf16.bf16.f32 "
        "{%0,%1,%2,%3}, {%4,%5,%6,%7}, {%8,%9}, {%0,%1,%2,%3};"
        : "+f"(c[0]), "+f"(c[1]), "+f"(c[2]), "+f"(c[3])
        : "r"(a[0]), "r"(a[1]), "r"(a[2]), "r"(a[3]), "r"(b[0]), "r"(b[1]));
}

// ---------------------------------------------------------------------------
// Conversion kernels: fp32 -> bf16 hi/lo split
// ---------------------------------------------------------------------------
__device__ __forceinline__ void split_bf16(float x, __nv_bfloat16& h, __nv_bfloat16& l) {
    h = __float2bfloat16(x);
    l = __float2bfloat16(x - __bfloat162float(h));
}

__global__ __launch_bounds__(256) void convert_A_kernel(const float* __restrict__ A) {
    size_t i = ((size_t)blockIdx.x * blockDim.x + threadIdx.x) * 4;
    if (i >= (size_t)MROWS * EDIM) return;
    float4 v = *(const float4*)&A[i];
    __nv_bfloat16 h0, l0, h1, l1, h2, l2, h3, l3;
    split_bf16(v.x, h0, l0); split_bf16(v.y, h1, l1);
    split_bf16(v.z, h2, l2); split_bf16(v.w, h3, l3);
    __nv_bfloat162* ph = (__nv_bfloat162*)&g_Ahi[i];
    __nv_bfloat162* pl = (__nv_bfloat162*)&g_Alo[i];
    ph[0] = __nv_bfloat162(h0, h1); ph[1] = __nv_bfloat162(h2, h3);
    pl[0] = __nv_bfloat162(l0, l1); pl[1] = __nv_bfloat162(l2, l3);
}

__global__ __launch_bounds__(256) void convert_W_kernel(
    const float* __restrict__ Wq, const float* __restrict__ Wk,
    const float* __restrict__ Wv, const float* __restrict__ Wr) {
    int id = blockIdx.x * blockDim.x + threadIdx.x;   // n*256 + k
    if (id >= NCOLS * EDIM) return;
    int n = id >> 8;
    int k = id & 255;
    const float* W = (n < 256) ? Wq : (n < 512) ? Wk : (n < 768) ? Wv : Wr;
    float x = W[(size_t)k * EDIM + (n & 255)];
    __nv_bfloat16 h, l;
    split_bf16(x, h, l);
    g_Bhi[(size_t)n * EDIM + k] = h;
    g_Blo[(size_t)n * EDIM + k] = l;
}

// ---------------------------------------------------------------------------
// Projection GEMM via mma.sync (split-bf16, 3 products).
// C[131072 x 1024] = A @ W.  CTA tile 128x128, warp tile 64x32, K chunks of 64.
// smem rows padded to stride 72 bf16 (144 B) -> conflict-free 32-bit frag LDS.
// ---------------------------------------------------------------------------
#define PSTR 72
#define PROJ_SMEM_BYTES (4 * 128 * PSTR * 2)   // 73728

__global__ __launch_bounds__(256, 2) void proj_mma_kernel() {
    extern __shared__ __nv_bfloat16 sm[];
    __nv_bfloat16* sAh = sm;
    __nv_bfloat16* sAl = sAh + 128 * PSTR;
    __nv_bfloat16* sBh = sAl + 128 * PSTR;
    __nv_bfloat16* sBl = sBh + 128 * PSTR;

    const int tid = threadIdx.x;
    const int wid = tid >> 5;
    const int lane = tid & 31;
    const int m0 = blockIdx.y * 128;
    const int n0 = blockIdx.x * 128;
    const int wm = (wid & 1) * 64;    // warp m offset in tile
    const int wn = (wid >> 1) * 32;   // warp n offset in tile
    const int grp = lane >> 2;        // 0..7
    const int tig = lane & 3;         // 0..3

    float acc[4][4][4];
#pragma unroll
    for (int mf = 0; mf < 4; mf++)
#pragma unroll
        for (int nf = 0; nf < 4; nf++)
#pragma unroll
            for (int r = 0; r < 4; r++) acc[mf][nf][r] = 0.f;

    for (int c = 0; c < EDIM / 64; c++) {
        const int k0 = c * 64;
        // Fill 4 tiles of 128 rows x 64 bf16 (8 uint4 per row), 4 uint4/thread/tile
#pragma unroll
        for (int s = 0; s < 4; s++) {
            int idx = tid + s * 256;          // 0..1023
            int r = idx >> 3;
            int c16 = idx & 7;
            size_t ga = (size_t)(m0 + r) * EDIM + k0 + c16 * 8;
            size_t gb = (size_t)(n0 + r) * EDIM + k0 + c16 * 8;
            *(uint4*)&sAh[r * PSTR + c16 * 8] = *(const uint4*)&g_Ahi[ga];
            *(uint4*)&sAl[r * PSTR + c16 * 8] = *(const uint4*)&g_Alo[ga];
            *(uint4*)&sBh[r * PSTR + c16 * 8] = *(const uint4*)&g_Bhi[gb];
            *(uint4*)&sBl[r * PSTR + c16 * 8] = *(const uint4*)&g_Blo[gb];
        }
        __syncthreads();

#pragma unroll
        for (int kk = 0; kk < 4; kk++) {
            const int kb = kk * 16 + tig * 2;
            uint32_t bh[4][2], bl[4][2];
#pragma unroll
            for (int nf = 0; nf < 4; nf++) {
                int n = wn + nf * 8 + grp;
                bh[nf][0] = *(const uint32_t*)&sBh[n * PSTR + kb];
                bh[nf][1] = *(const uint32_t*)&sBh[n * PSTR + kb + 8];
                bl[nf][0] = *(const uint32_t*)&sBl[n * PSTR + kb];
                bl[nf][1] = *(const uint32_t*)&sBl[n * PSTR + kb + 8];
            }
#pragma unroll
            for (int mf = 0; mf < 4; mf++) {
                int m = wm + mf * 16 + grp;
                uint32_t ah[4], al[4];
                ah[0] = *(const uint32_t*)&sAh[m * PSTR + kb];
                ah[1] = *(const uint32_t*)&sAh[(m + 8) * PSTR + kb];
                ah[2] = *(const uint32_t*)&sAh[m * PSTR + kb + 8];
                ah[3] = *(const uint32_t*)&sAh[(m + 8) * PSTR + kb + 8];
                al[0] = *(const uint32_t*)&sAl[m * PSTR + kb];
                al[1] = *(const uint32_t*)&sAl[(m + 8) * PSTR + kb];
                al[2] = *(const uint32_t*)&sAl[m * PSTR + kb + 8];
                al[3] = *(const uint32_t*)&sAl[(m + 8) * PSTR + kb + 8];
#pragma unroll
                for (int nf = 0; nf < 4; nf++) {
                    mma16816(acc[mf][nf], ah, bh[nf]);
                    mma16816(acc[mf][nf], ah, bl[nf]);
                    mma16816(acc[mf][nf], al, bh[nf]);
                }
            }
        }
        __syncthreads();
    }

    // Epilogue: write fp32 results
#pragma unroll
    for (int mf = 0; mf < 4; mf++) {
        int m = m0 + wm + mf * 16 + grp;
#pragma unroll
        for (int nf = 0; nf < 4; nf++) {
            int n = n0 + wn + nf * 8 + tig * 2;
            float2 v0 = make_float2(acc[mf][nf][0], acc[mf][nf][1]);
            float2 v1 = make_float2(acc[mf][nf][2], acc[mf][nf][3]);
            *(float2*)&g_qkvr[(size_t)m * NCOLS + n] = v0;
            *(float2*)&g_qkvr[(size_t)(m + 8) * NCOLS + n] = v1;
        }
    }
}

// ---------------------------------------------------------------------------
// Kernel B: attention per (b, h) — fp32 path (unchanged).
// ---------------------------------------------------------------------------
#define QSTRIDE 36
#define SSTRIDE 132
#define ATT_SMEM_FLOATS (3 * 128 * QSTRIDE + 128 * SSTRIDE)
#define ATT_SMEM_BYTES  (ATT_SMEM_FLOATS * 4)

__global__ __launch_bounds__(256, 1) void attn_kernel(float* __restrict__ out)
{
    extern __shared__ float smemf[];
    float* sQ = smemf;
    float* sK = sQ + 128 * QSTRIDE;
    float* sV = sK + 128 * QSTRIDE;
    float* sS = sV + 128 * QSTRIDE;

    const int bh = blockIdx.x;
    const int b = bh >> 3;
    const int h = bh & 7;
    const int tid = threadIdx.x;

    const size_t rowbase = (size_t)(b * FDIM) * NCOLS;
    const int colQ = h * DHEAD;

#pragma unroll
    for (int s = 0; s < 4; s++) {
        int idx = tid + s * 256;
        int r = idx >> 3;
        int c4 = (idx & 7) * 4;
        const float* src = &g_qkvr[rowbase + (size_t)r * NCOLS + colQ + c4];
        float4 q = *(const float4*)(src);
        float4 k = *(const float4*)(src + 256);
        float4 v = *(const float4*)(src + 512);
        *(float4*)&sQ[r * QSTRIDE + c4] = q;
        *(float4*)&sK[r * QSTRIDE + c4] = k;
        *(float4*)&sV[r * QSTRIDE + c4] = v;
    }
    __syncthreads();

    const int tx = tid & 15;
    const int ty = tid >> 4;
    float acc[8][8];
#pragma unroll
    for (int i = 0; i < 8; i++)
#pragma unroll
        for (int j = 0; j < 8; j++) acc[i][j] = 0.f;

#pragma unroll
    for (int d4 = 0; d4 < DHEAD; d4 += 4) {
        float4 kv[8];
#pragma unroll
        for (int j = 0; j < 8; j++)
            kv[j] = *(const float4*)&sK[(tx * 8 + j) * QSTRIDE + d4];
#pragma unroll
        for (int i = 0; i < 8; i++) {
            float4 q = *(const float4*)&sQ[(ty * 8 + i) * QSTRIDE + d4];
#pragma unroll
            for (int j = 0; j < 8; j++) {
                acc[i][j] = fmaf(q.x, kv[j].x, acc[i][j]);
                acc[i][j] = fmaf(q.y, kv[j].y, acc[i][j]);
                acc[i][j] = fmaf(q.z, kv[j].z, acc[i][j]);
                acc[i][j] = fmaf(q.w, kv[j].w, acc[i][j]);
            }
        }
    }

#pragma unroll
    for (int i = 0; i < 8; i++) {
        float m = acc[i][0];
#pragma unroll
        for (int j = 1; j < 8; j++) m = fmaxf(m, acc[i][j]);
#pragma unroll
        for (int o = 8; o >= 1; o >>= 1)
            m = fmaxf(m, __shfl_xor_sync(0xffffffffu, m, o));
        float ssum = 0.f;
#pragma unroll
        for (int j = 0; j < 8; j++) {
            float p = __expf(acc[i][j] - m);
            acc[i][j] = p;
            ssum += p;
        }
#pragma unroll
        for (int o = 8; o >= 1; o >>= 1)
            ssum += __shfl_xor_sync(0xffffffffu, ssum, o);
        float inv = 1.0f / ssum;
#pragma unroll
        for (int j = 0; j < 8; j++)
            sS[(ty * 8 + i) * SSTRIDE + tx * 8 + j] = acc[i][j] * inv;
    }
    __syncthreads();

    const int dgrp = tid & 15;
    const int rgrp = tid >> 4;
    float o0[8], o1[8];
#pragma unroll
    for (int i = 0; i < 8; i++) { o0[i] = 0.f; o1[i] = 0.f; }

#pragma unroll 4
    for (int j = 0; j < 128; j++) {
        float v0 = sV[j * QSTRIDE + dgrp * 2];
        float v1 = sV[j * QSTRIDE + dgrp * 2 + 1];
#pragma unroll
        for (int i = 0; i < 8; i++) {
            float p = sS[(rgrp * 8 + i) * SSTRIDE + j];
            o0[i] = fmaf(p, v0, o0[i]);
            o1[i] = fmaf(p, v1, o1[i]);
        }
    }

    const size_t orowbase = (size_t)(b * FDIM);
#pragma unroll
    for (int i = 0; i < 8; i++) {
        int r = rgrp * 8 + i;
        const float2 rr = *(const float2*)&g_qkvr[rowbase + (size_t)r * NCOLS + 768 + colQ + dgrp * 2];
        float2 res;
        res.x = fmaxf(o0[i] + rr.x, 0.f);
        res.y = fmaxf(o1[i] + rr.y, 0.f);
        *(float2*)&out[(orowbase + r) * EDIM + colQ + dgrp * 2] = res;
    }
}

// ---------------------------------------------------------------------------
// Launch
// ---------------------------------------------------------------------------
extern "C" void kernel_launch(void* const* d_in, const int* in_sizes, int n_in,
                              void* d_out, int out_size)
{
    const float* inputs = (const float*)d_in[0];
    const float* Wq     = (const float*)d_in[1];
    const float* Wk     = (const float*)d_in[2];
    const float* Wv     = (const float*)d_in[3];
    const float* Wr     = (const float*)d_in[4];
    float* out = (float*)d_out;

    cudaFuncSetAttribute(proj_mma_kernel, cudaFuncAttributeMaxDynamicSharedMemorySize,
                         PROJ_SMEM_BYTES);
    cudaFuncSetAttribute(attn_kernel, cudaFuncAttributeMaxDynamicSharedMemorySize,
                         ATT_SMEM_BYTES);

    // 1) split inputs and weights into bf16 hi/lo
    convert_A_kernel<<<(MROWS * EDIM / 4 + 255) / 256, 256>>>(inputs);
    convert_W_kernel<<<(NCOLS * EDIM + 255) / 256, 256>>>(Wq, Wk, Wv, Wr);

    // 2) fused projection GEMM on tensor cores (mma.sync, split-bf16)
    dim3 gridP(NCOLS / 128, MROWS / 128);   // 8 x 1024
    proj_mma_kernel<<<gridP, 256, PROJ_SMEM_BYTES>>>();

    // 3) attention + residual + relu
    attn_kernel<<<BATCH * HEADS, 256, ATT_SMEM_BYTES>>>(out);
}

// round 8
// speedup vs baseline: 2.3615x; 1.5161x over previous
#include <cuda_runtime.h>
#include <cuda_bf16.h>
#include <cstdint>
#include <math.h>

// Problem constants
#define BATCH 1024
#define FDIM  128
#define EDIM  256
#define HEADS 8
#define DHEAD 32
#define MROWS (BATCH * FDIM)   // 131072
#define NCOLS (4 * EDIM)       // 1024 : [Q | K | V | R]

// ---------------------------------------------------------------------------
// Device scratch (no allocations allowed)
// ---------------------------------------------------------------------------
__device__ float g_qkvr[(size_t)MROWS * NCOLS];                 // 537 MB
__device__ __nv_bfloat16 g_Ahi[(size_t)MROWS * EDIM];
__device__ __nv_bfloat16 g_Alo[(size_t)MROWS * EDIM];
__device__ __nv_bfloat16 g_Bhi[(size_t)NCOLS * EDIM];           // [n][k] = W[k][n]
__device__ __nv_bfloat16 g_Blo[(size_t)NCOLS * EDIM];

// ---------------------------------------------------------------------------
// mma.sync m16n8k16 bf16 -> f32
// ---------------------------------------------------------------------------
__device__ __forceinline__ void mma16816(float* c, const uint32_t* a, const uint32_t* b) {
    asm volatile(
        "mma.sync.aligned.m16n8k16.row.col.f32.bf16.bf16.f32 "
        "{%0,%1,%2,%3}, {%4,%5,%6,%7}, {%8,%9}, {%0,%1,%2,%3};"
        : "+f"(c[0]), "+f"(c[1]), "+f"(c[2]), "+f"(c[3])
        : "r"(a[0]), "r"(a[1]), "r"(a[2]), "r"(a[3]), "r"(b[0]), "r"(b[1]));
}

__device__ __forceinline__ void split_bf16(float x, __nv_bfloat16& h, __nv_bfloat16& l) {
    h = __float2bfloat16(x);
    l = __float2bfloat16(x - __bfloat162float(h));
}

// ---------------------------------------------------------------------------
// Conversion kernels
// ---------------------------------------------------------------------------
__global__ __launch_bounds__(256) void convert_A_kernel(const float* __restrict__ A) {
    size_t i = ((size_t)blockIdx.x * blockDim.x + threadIdx.x) * 4;
    if (i >= (size_t)MROWS * EDIM) return;
    float4 v = *(const float4*)&A[i];
    __nv_bfloat16 h0, l0, h1, l1, h2, l2, h3, l3;
    split_bf16(v.x, h0, l0); split_bf16(v.y, h1, l1);
    split_bf16(v.z, h2, l2); split_bf16(v.w, h3, l3);
    __nv_bfloat162* ph = (__nv_bfloat162*)&g_Ahi[i];
    __nv_bfloat162* pl = (__nv_bfloat162*)&g_Alo[i];
    ph[0] = __nv_bfloat162(h0, h1); ph[1] = __nv_bfloat162(h2, h3);
    pl[0] = __nv_bfloat162(l0, l1); pl[1] = __nv_bfloat162(l2, l3);
}

__global__ __launch_bounds__(256) void convert_W_kernel(
    const float* __restrict__ Wq, const float* __restrict__ Wk,
    const float* __restrict__ Wv, const float* __restrict__ Wr) {
    int id = blockIdx.x * blockDim.x + threadIdx.x;   // n*256 + k
    if (id >= NCOLS * EDIM) return;
    int n = id >> 8;
    int k = id & 255;
    const float* W = (n < 256) ? Wq : (n < 512) ? Wk : (n < 768) ? Wv : Wr;
    float x = W[(size_t)k * EDIM + (n & 255)];
    __nv_bfloat16 h, l;
    split_bf16(x, h, l);
    g_Bhi[(size_t)n * EDIM + k] = h;
    g_Blo[(size_t)n * EDIM + k] = l;
}

// ---------------------------------------------------------------------------
// Projection GEMM via mma.sync (split-bf16, 3 products). Unchanged from R3.
// ---------------------------------------------------------------------------
#define PSTR 72
#define PROJ_SMEM_BYTES (4 * 128 * PSTR * 2)   // 73728

__global__ __launch_bounds__(256, 2) void proj_mma_kernel() {
    extern __shared__ __nv_bfloat16 sm[];
    __nv_bfloat16* sAh = sm;
    __nv_bfloat16* sAl = sAh + 128 * PSTR;
    __nv_bfloat16* sBh = sAl + 128 * PSTR;
    __nv_bfloat16* sBl = sBh + 128 * PSTR;

    const int tid = threadIdx.x;
    const int wid = tid >> 5;
    const int lane = tid & 31;
    const int m0 = blockIdx.y * 128;
    const int n0 = blockIdx.x * 128;
    const int wm = (wid & 1) * 64;
    const int wn = (wid >> 1) * 32;
    const int grp = lane >> 2;
    const int tig = lane & 3;

    float acc[4][4][4];
#pragma unroll
    for (int mf = 0; mf < 4; mf++)
#pragma unroll
        for (int nf = 0; nf < 4; nf++)
#pragma unroll
            for (int r = 0; r < 4; r++) acc[mf][nf][r] = 0.f;

    for (int c = 0; c < EDIM / 64; c++) {
        const int k0 = c * 64;
#pragma unroll
        for (int s = 0; s < 4; s++) {
            int idx = tid + s * 256;
            int r = idx >> 3;
            int c16 = idx & 7;
            size_t ga = (size_t)(m0 + r) * EDIM + k0 + c16 * 8;
            size_t gb = (size_t)(n0 + r) * EDIM + k0 + c16 * 8;
            *(uint4*)&sAh[r * PSTR + c16 * 8] = *(const uint4*)&g_Ahi[ga];
            *(uint4*)&sAl[r * PSTR + c16 * 8] = *(const uint4*)&g_Alo[ga];
            *(uint4*)&sBh[r * PSTR + c16 * 8] = *(const uint4*)&g_Bhi[gb];
            *(uint4*)&sBl[r * PSTR + c16 * 8] = *(const uint4*)&g_Blo[gb];
        }
        __syncthreads();

#pragma unroll
        for (int kk = 0; kk < 4; kk++) {
            const int kb = kk * 16 + tig * 2;
            uint32_t bh[4][2], bl[4][2];
#pragma unroll
            for (int nf = 0; nf < 4; nf++) {
                int n = wn + nf * 8 + grp;
                bh[nf][0] = *(const uint32_t*)&sBh[n * PSTR + kb];
                bh[nf][1] = *(const uint32_t*)&sBh[n * PSTR + kb + 8];
                bl[nf][0] = *(const uint32_t*)&sBl[n * PSTR + kb];
                bl[nf][1] = *(const uint32_t*)&sBl[n * PSTR + kb + 8];
            }
#pragma unroll
            for (int mf = 0; mf < 4; mf++) {
                int m = wm + mf * 16 + grp;
                uint32_t ah[4], al[4];
                ah[0] = *(const uint32_t*)&sAh[m * PSTR + kb];
                ah[1] = *(const uint32_t*)&sAh[(m + 8) * PSTR + kb];
                ah[2] = *(const uint32_t*)&sAh[m * PSTR + kb + 8];
                ah[3] = *(const uint32_t*)&sAh[(m + 8) * PSTR + kb + 8];
                al[0] = *(const uint32_t*)&sAl[m * PSTR + kb];
                al[1] = *(const uint32_t*)&sAl[(m + 8) * PSTR + kb];
                al[2] = *(const uint32_t*)&sAl[m * PSTR + kb + 8];
                al[3] = *(const uint32_t*)&sAl[(m + 8) * PSTR + kb + 8];
#pragma unroll
                for (int nf = 0; nf < 4; nf++) {
                    mma16816(acc[mf][nf], ah, bh[nf]);
                    mma16816(acc[mf][nf], ah, bl[nf]);
                    mma16816(acc[mf][nf], al, bh[nf]);
                }
            }
        }
        __syncthreads();
    }

#pragma unroll
    for (int mf = 0; mf < 4; mf++) {
        int m = m0 + wm + mf * 16 + grp;
#pragma unroll
        for (int nf = 0; nf < 4; nf++) {
            int n = n0 + wn + nf * 8 + tig * 2;
            *(float2*)&g_qkvr[(size_t)m * NCOLS + n] = make_float2(acc[mf][nf][0], acc[mf][nf][1]);
            *(float2*)&g_qkvr[(size_t)(m + 8) * NCOLS + n] = make_float2(acc[mf][nf][2], acc[mf][nf][3]);
        }
    }
}

// ---------------------------------------------------------------------------
// Attention via mma.sync (split-bf16 for both S=QK^T and O=PV).
// One CTA per (b,h), 256 threads / 8 warps.
// ---------------------------------------------------------------------------
#define QKSTR 40     // bf16 stride for 128x32 Q/K tiles
#define VTSTR 136    // bf16 stride for 32x128 V^T tiles
#define SSTR  132    // fp32 stride for 128x128 S
#define PPSTR 136    // bf16 stride for 128x128 P tiles

// smem byte offsets
#define AOFF_QH  0
#define AOFF_QL  (AOFF_QH + 128 * QKSTR * 2)     // 10240
#define AOFF_KH  (AOFF_QL + 128 * QKSTR * 2)     // 20480
#define AOFF_KL  (AOFF_KH + 128 * QKSTR * 2)     // 30720
#define AOFF_VTH (AOFF_KL + 128 * QKSTR * 2)     // 40960
#define AOFF_VTL (AOFF_VTH + 32 * VTSTR * 2)     // 49664
#define AOFF_S   (AOFF_VTL + 32 * VTSTR * 2)     // 58368
#define AOFF_PH  (AOFF_S + 128 * SSTR * 4)       // 125952
#define AOFF_PL  (AOFF_PH + 128 * PPSTR * 2)     // 160768
#define ATT_SMEM_BYTES (AOFF_PL + 128 * PPSTR * 2)  // 195584

__global__ __launch_bounds__(256, 1) void attn_mma_kernel(float* __restrict__ out)
{
    extern __shared__ char asm_[];
    __nv_bfloat16* sQh = (__nv_bfloat16*)(asm_ + AOFF_QH);
    __nv_bfloat16* sQl = (__nv_bfloat16*)(asm_ + AOFF_QL);
    __nv_bfloat16* sKh = (__nv_bfloat16*)(asm_ + AOFF_KH);
    __nv_bfloat16* sKl = (__nv_bfloat16*)(asm_ + AOFF_KL);
    __nv_bfloat16* sVth = (__nv_bfloat16*)(asm_ + AOFF_VTH);
    __nv_bfloat16* sVtl = (__nv_bfloat16*)(asm_ + AOFF_VTL);
    float*         sS  = (float*)(asm_ + AOFF_S);
    __nv_bfloat16* sPh = (__nv_bfloat16*)(asm_ + AOFF_PH);
    __nv_bfloat16* sPl = (__nv_bfloat16*)(asm_ + AOFF_PL);

    const int bh = blockIdx.x;
    const int b = bh >> 3;
    const int h = bh & 7;
    const int tid = threadIdx.x;
    const int wid = tid >> 5;
    const int lane = tid & 31;
    const int grp = lane >> 2;
    const int tig = lane & 3;

    const size_t rowbase = (size_t)(b * FDIM) * NCOLS;
    const int colQ = h * DHEAD;

    // ---- load Q,K,V (fp32) -> split bf16 hi/lo smem tiles; V transposed ----
#pragma unroll
    for (int s = 0; s < 4; s++) {
        int idx = tid + s * 256;               // 0..1023
        int r = idx >> 3;                      // 0..127
        int c4 = (idx & 7) * 4;                // 0..28
        const float* src = &g_qkvr[rowbase + (size_t)r * NCOLS + colQ + c4];
        float4 q = *(const float4*)(src);
        float4 k = *(const float4*)(src + 256);
        float4 v = *(const float4*)(src + 512);
        __nv_bfloat16 h0, l0, h1, l1, h2, l2, h3, l3;
        split_bf16(q.x, h0, l0); split_bf16(q.y, h1, l1);
        split_bf16(q.z, h2, l2); split_bf16(q.w, h3, l3);
        *(__nv_bfloat162*)&sQh[r * QKSTR + c4]     = __nv_bfloat162(h0, h1);
        *(__nv_bfloat162*)&sQh[r * QKSTR + c4 + 2] = __nv_bfloat162(h2, h3);
        *(__nv_bfloat162*)&sQl[r * QKSTR + c4]     = __nv_bfloat162(l0, l1);
        *(__nv_bfloat162*)&sQl[r * QKSTR + c4 + 2] = __nv_bfloat162(l2, l3);
        split_bf16(k.x, h0, l0); split_bf16(k.y, h1, l1);
        split_bf16(k.z, h2, l2); split_bf16(k.w, h3, l3);
        *(__nv_bfloat162*)&sKh[r * QKSTR + c4]     = __nv_bfloat162(h0, h1);
        *(__nv_bfloat162*)&sKh[r * QKSTR + c4 + 2] = __nv_bfloat162(h2, h3);
        *(__nv_bfloat162*)&sKl[r * QKSTR + c4]     = __nv_bfloat162(l0, l1);
        *(__nv_bfloat162*)&sKl[r * QKSTR + c4 + 2] = __nv_bfloat162(l2, l3);
        split_bf16(v.x, h0, l0); split_bf16(v.y, h1, l1);
        split_bf16(v.z, h2, l2); split_bf16(v.w, h3, l3);
        sVth[(c4 + 0) * VTSTR + r] = h0; sVtl[(c4 + 0) * VTSTR + r] = l0;
        sVth[(c4 + 1) * VTSTR + r] = h1; sVtl[(c4 + 1) * VTSTR + r] = l1;
        sVth[(c4 + 2) * VTSTR + r] = h2; sVtl[(c4 + 2) * VTSTR + r] = l2;
        sVth[(c4 + 3) * VTSTR + r] = h3; sVtl[(c4 + 3) * VTSTR + r] = l3;
    }
    __syncthreads();

    // ---- S = Q K^T  (warp tile 64x32; 2x4 warp grid) ----
    {
        const int wm = (wid >> 2) * 64;
        const int wn = (wid & 3) * 32;
        float acc[4][4][4];
#pragma unroll
        for (int mf = 0; mf < 4; mf++)
#pragma unroll
            for (int nf = 0; nf < 4; nf++)
#pragma unroll
                for (int r = 0; r < 4; r++) acc[mf][nf][r] = 0.f;

#pragma unroll
        for (int kk = 0; kk < 2; kk++) {
            const int kb = kk * 16 + tig * 2;
            uint32_t bhf[4][2], blf[4][2];
#pragma unroll
            for (int nf = 0; nf < 4; nf++) {
                int n = wn + nf * 8 + grp;
                bhf[nf][0] = *(const uint32_t*)&sKh[n * QKSTR + kb];
                bhf[nf][1] = *(const uint32_t*)&sKh[n * QKSTR + kb + 8];
                blf[nf][0] = *(const uint32_t*)&sKl[n * QKSTR + kb];
                blf[nf][1] = *(const uint32_t*)&sKl[n * QKSTR + kb + 8];
            }
#pragma unroll
            for (int mf = 0; mf < 4; mf++) {
                int m = wm + mf * 16 + grp;
                uint32_t ah[4], al[4];
                ah[0] = *(const uint32_t*)&sQh[m * QKSTR + kb];
                ah[1] = *(const uint32_t*)&sQh[(m + 8) * QKSTR + kb];
                ah[2] = *(const uint32_t*)&sQh[m * QKSTR + kb + 8];
                ah[3] = *(const uint32_t*)&sQh[(m + 8) * QKSTR + kb + 8];
                al[0] = *(const uint32_t*)&sQl[m * QKSTR + kb];
                al[1] = *(const uint32_t*)&sQl[(m + 8) * QKSTR + kb];
                al[2] = *(const uint32_t*)&sQl[m * QKSTR + kb + 8];
                al[3] = *(const uint32_t*)&sQl[(m + 8) * QKSTR + kb + 8];
#pragma unroll
                for (int nf = 0; nf < 4; nf++) {
                    mma16816(acc[mf][nf], ah, bhf[nf]);
                    mma16816(acc[mf][nf], ah, blf[nf]);
                    mma16816(acc[mf][nf], al, bhf[nf]);
                }
            }
        }
        // stage raw fp32 scores
#pragma unroll
        for (int mf = 0; mf < 4; mf++) {
            int r0 = wm + mf * 16 + grp;
#pragma unroll
            for (int nf = 0; nf < 4; nf++) {
                int cc = wn + nf * 8 + tig * 2;
                *(float2*)&sS[r0 * SSTR + cc]       = make_float2(acc[mf][nf][0], acc[mf][nf][1]);
                *(float2*)&sS[(r0 + 8) * SSTR + cc] = make_float2(acc[mf][nf][2], acc[mf][nf][3]);
            }
        }
    }
    __syncthreads();

    // ---- row softmax: warp w handles rows 16w..16w+15 ----
#pragma unroll
    for (int r = 0; r < 16; r++) {
        int row = wid * 16 + r;
        float4 v = *(const float4*)&sS[row * SSTR + lane * 4];
        float m = fmaxf(fmaxf(v.x, v.y), fmaxf(v.z, v.w));
#pragma unroll
        for (int o = 16; o >= 1; o >>= 1)
            m = fmaxf(m, __shfl_xor_sync(0xffffffffu, m, o));
        float e0 = __expf(v.x - m), e1 = __expf(v.y - m);
        float e2 = __expf(v.z - m), e3 = __expf(v.w - m);
        float s = e0 + e1 + e2 + e3;
#pragma unroll
        for (int o = 16; o >= 1; o >>= 1)
            s += __shfl_xor_sync(0xffffffffu, s, o);
        float inv = 1.0f / s;
        e0 *= inv; e1 *= inv; e2 *= inv; e3 *= inv;
        __nv_bfloat16 h0, l0, h1, l1, h2, l2, h3, l3;
        split_bf16(e0, h0, l0); split_bf16(e1, h1, l1);
        split_bf16(e2, h2, l2); split_bf16(e3, h3, l3);
        *(__nv_bfloat162*)&sPh[row * PPSTR + lane * 4]     = __nv_bfloat162(h0, h1);
        *(__nv_bfloat162*)&sPh[row * PPSTR + lane * 4 + 2] = __nv_bfloat162(h2, h3);
        *(__nv_bfloat162*)&sPl[row * PPSTR + lane * 4]     = __nv_bfloat162(l0, l1);
        *(__nv_bfloat162*)&sPl[row * PPSTR + lane * 4 + 2] = __nv_bfloat162(l2, l3);
    }
    __syncthreads();

    // ---- O = P V  (warp tile 16x32) + residual + relu ----
    {
        const int wm2 = wid * 16;
        float acc2[4][4];
#pragma unroll
        for (int nf = 0; nf < 4; nf++)
#pragma unroll
            for (int r = 0; r < 4; r++) acc2[nf][r] = 0.f;

#pragma unroll
        for (int kk = 0; kk < 8; kk++) {
            const int kb = kk * 16 + tig * 2;
            uint32_t bhf[4][2], blf[4][2];
#pragma unroll
            for (int nf = 0; nf < 4; nf++) {
                int n = nf * 8 + grp;
                bhf[nf][0] = *(const uint32_t*)&sVth[n * VTSTR + kb];
                bhf[nf][1] = *(const uint32_t*)&sVth[n * VTSTR + kb + 8];
                blf[nf][0] = *(const uint32_t*)&sVtl[n * VTSTR + kb];
                blf[nf][1] = *(const uint32_t*)&sVtl[n * VTSTR + kb + 8];
            }
            int m = wm2 + grp;
            uint32_t ah[4], al[4];
            ah[0] = *(const uint32_t*)&sPh[m * PPSTR + kb];
            ah[1] = *(const uint32_t*)&sPh[(m + 8) * PPSTR + kb];
            ah[2] = *(const uint32_t*)&sPh[m * PPSTR + kb + 8];
            ah[3] = *(const uint32_t*)&sPh[(m + 8) * PPSTR + kb + 8];
            al[0] = *(const uint32_t*)&sPl[m * PPSTR + kb];
            al[1] = *(const uint32_t*)&sPl[(m + 8) * PPSTR + kb];
            al[2] = *(const uint32_t*)&sPl[m * PPSTR + kb + 8];
            al[3] = *(const uint32_t*)&sPl[(m + 8) * PPSTR + kb + 8];
#pragma unroll
            for (int nf = 0; nf < 4; nf++) {
                mma16816(acc2[nf], ah, bhf[nf]);
                mma16816(acc2[nf], ah, blf[nf]);
                mma16816(acc2[nf], al, bhf[nf]);
            }
        }

        // epilogue
        const size_t orowbase = (size_t)(b * FDIM);
#pragma unroll
        for (int nf = 0; nf < 4; nf++) {
            int cc = nf * 8 + tig * 2;
            int r0 = wm2 + grp;
            int r1 = r0 + 8;
            float2 rr0 = *(const float2*)&g_qkvr[rowbase + (size_t)r0 * NCOLS + 768 + colQ + cc];
            float2 rr1 = *(const float2*)&g_qkvr[rowbase + (size_t)r1 * NCOLS + 768 + colQ + cc];
            float2 o0, o1;
            o0.x = fmaxf(acc2[nf][0] + rr0.x, 0.f);
            o0.y = fmaxf(acc2[nf][1] + rr0.y, 0.f);
            o1.x = fmaxf(acc2[nf][2] + rr1.x, 0.f);
            o1.y = fmaxf(acc2[nf][3] + rr1.y, 0.f);
            *(float2*)&out[(orowbase + r0) * EDIM + colQ + cc] = o0;
            *(float2*)&out[(orowbase + r1) * EDIM + colQ + cc] = o1;
        }
    }
}

// ---------------------------------------------------------------------------
// Launch
// ---------------------------------------------------------------------------
extern "C" void kernel_launch(void* const* d_in, const int* in_sizes, int n_in,
                              void* d_out, int out_size)
{
    const float* inputs = (const float*)d_in[0];
    const float* Wq     = (const float*)d_in[1];
    const float* Wk     = (const float*)d_in[2];
    const float* Wv     = (const float*)d_in[3];
    const float* Wr     = (const float*)d_in[4];
    float* out = (float*)d_out;

    cudaFuncSetAttribute(proj_mma_kernel, cudaFuncAttributeMaxDynamicSharedMemorySize,
                         PROJ_SMEM_BYTES);
    cudaFuncSetAttribute(attn_mma_kernel, cudaFuncAttributeMaxDynamicSharedMemorySize,
                         ATT_SMEM_BYTES);

    convert_A_kernel<<<(MROWS * EDIM / 4 + 255) / 256, 256>>>(inputs);
    convert_W_kernel<<<(NCOLS * EDIM + 255) / 256, 256>>>(Wq, Wk, Wv, Wr);

    dim3 gridP(NCOLS / 128, MROWS / 128);   // 8 x 1024
    proj_mma_kernel<<<gridP, 256, PROJ_SMEM_BYTES>>>();

    attn_mma_kernel<<<BATCH * HEADS, 256, ATT_SMEM_BYTES>>>(out);
}

// round 9
// speedup vs baseline: 3.3471x; 1.4174x over previous
#include <cuda_runtime.h>
#include <cuda_bf16.h>
#include <cstdint>
#include <math.h>

// Problem constants
#define BATCH 1024
#define FDIM  128
#define EDIM  256
#define HEADS 8
#define DHEAD 32
#define MROWS (BATCH * FDIM)   // 131072
#define NCOLS (4 * EDIM)       // 1024 : [Q | K | V | R]

// ---------------------------------------------------------------------------
// Device scratch (no allocations allowed)
// ---------------------------------------------------------------------------
__device__ float g_qkvr[(size_t)MROWS * NCOLS];                 // 537 MB
__device__ __nv_bfloat16 g_Ahi[(size_t)MROWS * EDIM];
__device__ __nv_bfloat16 g_Alo[(size_t)MROWS * EDIM];
__device__ __nv_bfloat16 g_Bhi[(size_t)NCOLS * EDIM];           // [n][k] = W[k][n]
__device__ __nv_bfloat16 g_Blo[(size_t)NCOLS * EDIM];

// ---------------------------------------------------------------------------
// mma.sync m16n8k16 bf16 -> f32
// ---------------------------------------------------------------------------
__device__ __forceinline__ void mma16816(float* c, const uint32_t* a, const uint32_t* b) {
    asm volatile(
        "mma.sync.aligned.m16n8k16.row.col.f32.bf16.bf16.f32 "
        "{%0,%1,%2,%3}, {%4,%5,%6,%7}, {%8,%9}, {%0,%1,%2,%3};"
        : "+f"(c[0]), "+f"(c[1]), "+f"(c[2]), "+f"(c[3])
        : "r"(a[0]), "r"(a[1]), "r"(a[2]), "r"(a[3]), "r"(b[0]), "r"(b[1]));
}

__device__ __forceinline__ void split_bf16(float x, __nv_bfloat16& h, __nv_bfloat16& l) {
    h = __float2bfloat16(x);
    l = __float2bfloat16(x - __bfloat162float(h));
}

__device__ __forceinline__ uint32_t pack2(__nv_bfloat16 a, __nv_bfloat16 b) {
    __nv_bfloat162 t(a, b);   // a in low 16 bits (lower k index)
    return *(uint32_t*)&t;
}

// ---------------------------------------------------------------------------
// Conversion kernels
// ---------------------------------------------------------------------------
__global__ __launch_bounds__(256) void convert_A_kernel(const float* __restrict__ A) {
    size_t i = ((size_t)blockIdx.x * blockDim.x + threadIdx.x) * 4;
    if (i >= (size_t)MROWS * EDIM) return;
    float4 v = *(const float4*)&A[i];
    __nv_bfloat16 h0, l0, h1, l1, h2, l2, h3, l3;
    split_bf16(v.x, h0, l0); split_bf16(v.y, h1, l1);
    split_bf16(v.z, h2, l2); split_bf16(v.w, h3, l3);
    __nv_bfloat162* ph = (__nv_bfloat162*)&g_Ahi[i];
    __nv_bfloat162* pl = (__nv_bfloat162*)&g_Alo[i];
    ph[0] = __nv_bfloat162(h0, h1); ph[1] = __nv_bfloat162(h2, h3);
    pl[0] = __nv_bfloat162(l0, l1); pl[1] = __nv_bfloat162(l2, l3);
}

__global__ __launch_bounds__(256) void convert_W_kernel(
    const float* __restrict__ Wq, const float* __restrict__ Wk,
    const float* __restrict__ Wv, const float* __restrict__ Wr) {
    int id = blockIdx.x * blockDim.x + threadIdx.x;   // n*256 + k
    if (id >= NCOLS * EDIM) return;
    int n = id >> 8;
    int k = id & 255;
    const float* W = (n < 256) ? Wq : (n < 512) ? Wk : (n < 768) ? Wv : Wr;
    float x = W[(size_t)k * EDIM + (n & 255)];
    __nv_bfloat16 h, l;
    split_bf16(x, h, l);
    g_Bhi[(size_t)n * EDIM + k] = h;
    g_Blo[(size_t)n * EDIM + k] = l;
}

// ---------------------------------------------------------------------------
// Projection GEMM via mma.sync (split-bf16, 3 products). Unchanged.
// ---------------------------------------------------------------------------
#define PSTR 72
#define PROJ_SMEM_BYTES (4 * 128 * PSTR * 2)   // 73728

__global__ __launch_bounds__(256, 2) void proj_mma_kernel() {
    extern __shared__ __nv_bfloat16 sm[];
    __nv_bfloat16* sAh = sm;
    __nv_bfloat16* sAl = sAh + 128 * PSTR;
    __nv_bfloat16* sBh = sAl + 128 * PSTR;
    __nv_bfloat16* sBl = sBh + 128 * PSTR;

    const int tid = threadIdx.x;
    const int wid = tid >> 5;
    const int lane = tid & 31;
    const int m0 = blockIdx.y * 128;
    const int n0 = blockIdx.x * 128;
    const int wm = (wid & 1) * 64;
    const int wn = (wid >> 1) * 32;
    const int grp = lane >> 2;
    const int tig = lane & 3;

    float acc[4][4][4];
#pragma unroll
    for (int mf = 0; mf < 4; mf++)
#pragma unroll
        for (int nf = 0; nf < 4; nf++)
#pragma unroll
            for (int r = 0; r < 4; r++) acc[mf][nf][r] = 0.f;

    for (int c = 0; c < EDIM / 64; c++) {
        const int k0 = c * 64;
#pragma unroll
        for (int s = 0; s < 4; s++) {
            int idx = tid + s * 256;
            int r = idx >> 3;
            int c16 = idx & 7;
            size_t ga = (size_t)(m0 + r) * EDIM + k0 + c16 * 8;
            size_t gb = (size_t)(n0 + r) * EDIM + k0 + c16 * 8;
            *(uint4*)&sAh[r * PSTR + c16 * 8] = *(const uint4*)&g_Ahi[ga];
            *(uint4*)&sAl[r * PSTR + c16 * 8] = *(const uint4*)&g_Alo[ga];
            *(uint4*)&sBh[r * PSTR + c16 * 8] = *(const uint4*)&g_Bhi[gb];
            *(uint4*)&sBl[r * PSTR + c16 * 8] = *(const uint4*)&g_Blo[gb];
        }
        __syncthreads();

#pragma unroll
        for (int kk = 0; kk < 4; kk++) {
            const int kb = kk * 16 + tig * 2;
            uint32_t bh[4][2], bl[4][2];
#pragma unroll
            for (int nf = 0; nf < 4; nf++) {
                int n = wn + nf * 8 + grp;
                bh[nf][0] = *(const uint32_t*)&sBh[n * PSTR + kb];
                bh[nf][1] = *(const uint32_t*)&sBh[n * PSTR + kb + 8];
                bl[nf][0] = *(const uint32_t*)&sBl[n * PSTR + kb];
                bl[nf][1] = *(const uint32_t*)&sBl[n * PSTR + kb + 8];
            }
#pragma unroll
            for (int mf = 0; mf < 4; mf++) {
                int m = wm + mf * 16 + grp;
                uint32_t ah[4], al[4];
                ah[0] = *(const uint32_t*)&sAh[m * PSTR + kb];
                ah[1] = *(const uint32_t*)&sAh[(m + 8) * PSTR + kb];
                ah[2] = *(const uint32_t*)&sAh[m * PSTR + kb + 8];
                ah[3] = *(const uint32_t*)&sAh[(m + 8) * PSTR + kb + 8];
                al[0] = *(const uint32_t*)&sAl[m * PSTR + kb];
                al[1] = *(const uint32_t*)&sAl[(m + 8) * PSTR + kb];
                al[2] = *(const uint32_t*)&sAl[m * PSTR + kb + 8];
                al[3] = *(const uint32_t*)&sAl[(m + 8) * PSTR + kb + 8];
#pragma unroll
                for (int nf = 0; nf < 4; nf++) {
                    mma16816(acc[mf][nf], ah, bh[nf]);
                    mma16816(acc[mf][nf], ah, bl[nf]);
                    mma16816(acc[mf][nf], al, bh[nf]);
                }
            }
        }
        __syncthreads();
    }

#pragma unroll
    for (int mf = 0; mf < 4; mf++) {
        int m = m0 + wm + mf * 16 + grp;
#pragma unroll
        for (int nf = 0; nf < 4; nf++) {
            int n = n0 + wn + nf * 8 + tig * 2;
            *(float2*)&g_qkvr[(size_t)m * NCOLS + n] = make_float2(acc[mf][nf][0], acc[mf][nf][1]);
            *(float2*)&g_qkvr[(size_t)(m + 8) * NCOLS + n] = make_float2(acc[mf][nf][2], acc[mf][nf][3]);
        }
    }
}

// ---------------------------------------------------------------------------
// Attention, register-resident S/P version.
// One CTA per (b,h), 8 warps; each warp owns 16 complete rows (m = wid*16).
//   S = Q K^T : per warp m16 x n128 (16 n8-fragments), split-bf16 3 products.
//   Softmax entirely in registers (quad shuffles xor 1,2).
//   P fragments re-packed in registers into A-fragment layout (no smem).
//   O = P V via V^T tiles in smem.
// Smem: Q hi/lo, K hi/lo (128x32, stride 40), V^T hi/lo (32x128, stride 136).
// ---------------------------------------------------------------------------
#define QKSTR 40
#define VTSTR 136
#define AOFF_QH  0
#define AOFF_QL  (AOFF_QH + 128 * QKSTR * 2)     // 10240
#define AOFF_KH  (AOFF_QL + 128 * QKSTR * 2)     // 20480
#define AOFF_KL  (AOFF_KH + 128 * QKSTR * 2)     // 30720
#define AOFF_VTH (AOFF_KL + 128 * QKSTR * 2)     // 40960
#define AOFF_VTL (AOFF_VTH + 32 * VTSTR * 2)     // 49664
#define ATT_SMEM_BYTES (AOFF_VTL + 32 * VTSTR * 2)  // 58368

__global__ __launch_bounds__(256, 2) void attn_mma_kernel(float* __restrict__ out)
{
    extern __shared__ char asm_[];
    __nv_bfloat16* sQh  = (__nv_bfloat16*)(asm_ + AOFF_QH);
    __nv_bfloat16* sQl  = (__nv_bfloat16*)(asm_ + AOFF_QL);
    __nv_bfloat16* sKh  = (__nv_bfloat16*)(asm_ + AOFF_KH);
    __nv_bfloat16* sKl  = (__nv_bfloat16*)(asm_ + AOFF_KL);
    __nv_bfloat16* sVth = (__nv_bfloat16*)(asm_ + AOFF_VTH);
    __nv_bfloat16* sVtl = (__nv_bfloat16*)(asm_ + AOFF_VTL);

    const int bh = blockIdx.x;
    const int b = bh >> 3;
    const int h = bh & 7;
    const int tid = threadIdx.x;
    const int wid = tid >> 5;
    const int lane = tid & 31;
    const int grp = lane >> 2;
    const int tig = lane & 3;

    const size_t rowbase = (size_t)(b * FDIM) * NCOLS;
    const int colQ = h * DHEAD;

    // ---- load Q,K,V (fp32) -> split bf16 hi/lo smem tiles; V transposed ----
#pragma unroll
    for (int s = 0; s < 4; s++) {
        int idx = tid + s * 256;               // 0..1023
        int r = idx >> 3;                      // 0..127
        int c4 = (idx & 7) * 4;                // 0..28
        const float* src = &g_qkvr[rowbase + (size_t)r * NCOLS + colQ + c4];
        float4 q = *(const float4*)(src);
        float4 k = *(const float4*)(src + 256);
        float4 v = *(const float4*)(src + 512);
        __nv_bfloat16 h0, l0, h1, l1, h2, l2, h3, l3;
        split_bf16(q.x, h0, l0); split_bf16(q.y, h1, l1);
        split_bf16(q.z, h2, l2); split_bf16(q.w, h3, l3);
        *(__nv_bfloat162*)&sQh[r * QKSTR + c4]     = __nv_bfloat162(h0, h1);
        *(__nv_bfloat162*)&sQh[r * QKSTR + c4 + 2] = __nv_bfloat162(h2, h3);
        *(__nv_bfloat162*)&sQl[r * QKSTR + c4]     = __nv_bfloat162(l0, l1);
        *(__nv_bfloat162*)&sQl[r * QKSTR + c4 + 2] = __nv_bfloat162(l2, l3);
        split_bf16(k.x, h0, l0); split_bf16(k.y, h1, l1);
        split_bf16(k.z, h2, l2); split_bf16(k.w, h3, l3);
        *(__nv_bfloat162*)&sKh[r * QKSTR + c4]     = __nv_bfloat162(h0, h1);
        *(__nv_bfloat162*)&sKh[r * QKSTR + c4 + 2] = __nv_bfloat162(h2, h3);
        *(__nv_bfloat162*)&sKl[r * QKSTR + c4]     = __nv_bfloat162(l0, l1);
        *(__nv_bfloat162*)&sKl[r * QKSTR + c4 + 2] = __nv_bfloat162(l2, l3);
        split_bf16(v.x, h0, l0); split_bf16(v.y, h1, l1);
        split_bf16(v.z, h2, l2); split_bf16(v.w, h3, l3);
        sVth[(c4 + 0) * VTSTR + r] = h0; sVtl[(c4 + 0) * VTSTR + r] = l0;
        sVth[(c4 + 1) * VTSTR + r] = h1; sVtl[(c4 + 1) * VTSTR + r] = l1;
        sVth[(c4 + 2) * VTSTR + r] = h2; sVtl[(c4 + 2) * VTSTR + r] = l2;
        sVth[(c4 + 3) * VTSTR + r] = h3; sVtl[(c4 + 3) * VTSTR + r] = l3;
    }
    __syncthreads();

    // ---- S = Q K^T : warp wid handles rows wm..wm+15, all 128 cols ----
    const int wm = wid * 16;
    float acc[16][4];
#pragma unroll
    for (int nf = 0; nf < 16; nf++)
#pragma unroll
        for (int r = 0; r < 4; r++) acc[nf][r] = 0.f;

#pragma unroll
    for (int kk = 0; kk < 2; kk++) {
        const int kb = kk * 16 + tig * 2;
        const int m = wm + grp;
        uint32_t ah[4], al[4];
        ah[0] = *(const uint32_t*)&sQh[m * QKSTR + kb];
        ah[1] = *(const uint32_t*)&sQh[(m + 8) * QKSTR + kb];
        ah[2] = *(const uint32_t*)&sQh[m * QKSTR + kb + 8];
        ah[3] = *(const uint32_t*)&sQh[(m + 8) * QKSTR + kb + 8];
        al[0] = *(const uint32_t*)&sQl[m * QKSTR + kb];
        al[1] = *(const uint32_t*)&sQl[(m + 8) * QKSTR + kb];
        al[2] = *(const uint32_t*)&sQl[m * QKSTR + kb + 8];
        al[3] = *(const uint32_t*)&sQl[(m + 8) * QKSTR + kb + 8];
#pragma unroll
        for (int nf = 0; nf < 16; nf++) {
            int n = nf * 8 + grp;
            uint32_t bhf[2], blf[2];
            bhf[0] = *(const uint32_t*)&sKh[n * QKSTR + kb];
            bhf[1] = *(const uint32_t*)&sKh[n * QKSTR + kb + 8];
            blf[0] = *(const uint32_t*)&sKl[n * QKSTR + kb];
            blf[1] = *(const uint32_t*)&sKl[n * QKSTR + kb + 8];
            mma16816(acc[nf], ah, bhf);
            mma16816(acc[nf], ah, blf);
            mma16816(acc[nf], al, bhf);
        }
    }

    // ---- softmax in registers ----
    // Thread holds: row lo = wm+grp  -> acc[nf][0], acc[nf][1]  (cols 8nf+2tig, +1)
    //               row hi = wm+grp+8 -> acc[nf][2], acc[nf][3]
    float mx0 = -1e30f, mx1 = -1e30f;
#pragma unroll
    for (int nf = 0; nf < 16; nf++) {
        mx0 = fmaxf(mx0, fmaxf(acc[nf][0], acc[nf][1]));
        mx1 = fmaxf(mx1, fmaxf(acc[nf][2], acc[nf][3]));
    }
#pragma unroll
    for (int o = 2; o >= 1; o >>= 1) {
        mx0 = fmaxf(mx0, __shfl_xor_sync(0xffffffffu, mx0, o));
        mx1 = fmaxf(mx1, __shfl_xor_sync(0xffffffffu, mx1, o));
    }
    float s0 = 0.f, s1 = 0.f;
#pragma unroll
    for (int nf = 0; nf < 16; nf++) {
        acc[nf][0] = __expf(acc[nf][0] - mx0);
        acc[nf][1] = __expf(acc[nf][1] - mx0);
        acc[nf][2] = __expf(acc[nf][2] - mx1);
        acc[nf][3] = __expf(acc[nf][3] - mx1);
        s0 += acc[nf][0] + acc[nf][1];
        s1 += acc[nf][2] + acc[nf][3];
    }
#pragma unroll
    for (int o = 2; o >= 1; o >>= 1) {
        s0 += __shfl_xor_sync(0xffffffffu, s0, o);
        s1 += __shfl_xor_sync(0xffffffffu, s1, o);
    }
    const float inv0 = 1.0f / s0;
    const float inv1 = 1.0f / s1;

    // ---- pack P into A-fragments (hi/lo), consuming acc ----
    // k16 block j uses n8 fragments 2j (k=16j..16j+7) and 2j+1 (k=16j+8..).
    uint32_t ph[8][4], pl[8][4];
#pragma unroll
    for (int j = 0; j < 8; j++) {
        float p00 = acc[2 * j][0] * inv0,     p01 = acc[2 * j][1] * inv0;
        float p02 = acc[2 * j][2] * inv1,     p03 = acc[2 * j][3] * inv1;
        float p10 = acc[2 * j + 1][0] * inv0, p11 = acc[2 * j + 1][1] * inv0;
        float p12 = acc[2 * j + 1][2] * inv1, p13 = acc[2 * j + 1][3] * inv1;
        __nv_bfloat16 ha, la, hb, lb;
        split_bf16(p00, ha, la); split_bf16(p01, hb, lb);
        ph[j][0] = pack2(ha, hb); pl[j][0] = pack2(la, lb);
        split_bf16(p02, ha, la); split_bf16(p03, hb, lb);
        ph[j][1] = pack2(ha, hb); pl[j][1] = pack2(la, lb);
        split_bf16(p10, ha, la); split_bf16(p11, hb, lb);
        ph[j][2] = pack2(ha, hb); pl[j][2] = pack2(la, lb);
        split_bf16(p12, ha, la); split_bf16(p13, hb, lb);
        ph[j][3] = pack2(ha, hb); pl[j][3] = pack2(la, lb);
    }

    // ---- O = P V : warp tile m16 x n32, k=128 (8 k16 blocks) ----
    float o[4][4];
#pragma unroll
    for (int nf = 0; nf < 4; nf++)
#pragma unroll
        for (int r = 0; r < 4; r++) o[nf][r] = 0.f;

#pragma unroll
    for (int kk = 0; kk < 8; kk++) {
        const int kb = kk * 16 + tig * 2;
#pragma unroll
        for (int nf = 0; nf < 4; nf++) {
            int n = nf * 8 + grp;
            uint32_t bhf[2], blf[2];
            bhf[0] = *(const uint32_t*)&sVth[n * VTSTR + kb];
            bhf[1] = *(const uint32_t*)&sVth[n * VTSTR + kb + 8];
            blf[0] = *(const uint32_t*)&sVtl[n * VTSTR + kb];
            blf[1] = *(const uint32_t*)&sVtl[n * VTSTR + kb + 8];
            mma16816(o[nf], ph[kk], bhf);
            mma16816(o[nf], ph[kk], blf);
            mma16816(o[nf], pl[kk], bhf);
        }
    }

    // ---- epilogue: + residual, ReLU, store ----
    const size_t orowbase = (size_t)(b * FDIM);
#pragma unroll
    for (int nf = 0; nf < 4; nf++) {
        int cc = nf * 8 + tig * 2;
        int r0 = wm + grp;
        int r1 = r0 + 8;
        float2 rr0 = *(const float2*)&g_qkvr[rowbase + (size_t)r0 * NCOLS + 768 + colQ + cc];
        float2 rr1 = *(const float2*)&g_qkvr[rowbase + (size_t)r1 * NCOLS + 768 + colQ + cc];
        float2 o0, o1;
        o0.x = fmaxf(o[nf][0] + rr0.x, 0.f);
        o0.y = fmaxf(o[nf][1] + rr0.y, 0.f);
        o1.x = fmaxf(o[nf][2] + rr1.x, 0.f);
        o1.y = fmaxf(o[nf][3] + rr1.y, 0.f);
        *(float2*)&out[(orowbase + r0) * EDIM + colQ + cc] = o0;
        *(float2*)&out[(orowbase + r1) * EDIM + colQ + cc] = o1;
    }
}

// ---------------------------------------------------------------------------
// Launch
// ---------------------------------------------------------------------------
extern "C" void kernel_launch(void* const* d_in, const int* in_sizes, int n_in,
                              void* d_out, int out_size)
{
    const float* inputs = (const float*)d_in[0];
    const float* Wq     = (const float*)d_in[1];
    const float* Wk     = (const float*)d_in[2];
    const float* Wv     = (const float*)d_in[3];
    const float* Wr     = (const float*)d_in[4];
    float* out = (float*)d_out;

    cudaFuncSetAttribute(proj_mma_kernel, cudaFuncAttributeMaxDynamicSharedMemorySize,
                         PROJ_SMEM_BYTES);
    cudaFuncSetAttribute(attn_mma_kernel, cudaFuncAttributeMaxDynamicSharedMemorySize,
                         ATT_SMEM_BYTES);

    convert_A_kernel<<<(MROWS * EDIM / 4 + 255) / 256, 256>>>(inputs);
    convert_W_kernel<<<(NCOLS * EDIM + 255) / 256, 256>>>(Wq, Wk, Wv, Wr);

    dim3 gridP(NCOLS / 128, MROWS / 128);   // 8 x 1024
    proj_mma_kernel<<<gridP, 256, PROJ_SMEM_BYTES>>>();

    attn_mma_kernel<<<BATCH * HEADS, 256, ATT_SMEM_BYTES>>>(out);
}

// round 10
// speedup vs baseline: 4.4086x; 1.3172x over previous
#include <cuda_runtime.h>
#include <cuda_fp16.h>
#include <cstdint>
#include <math.h>

// Problem constants
#define BATCH 1024
#define FDIM  128
#define EDIM  256
#define HEADS 8
#define DHEAD 32
#define MROWS (BATCH * FDIM)   // 131072
#define NCOLS (4 * EDIM)       // 1024 : [Q | K | V | R]

// ---------------------------------------------------------------------------
// Device scratch (no allocations allowed)
// ---------------------------------------------------------------------------
__device__ float g_qkvr[(size_t)MROWS * NCOLS];          // 537 MB fp32 Q|K|V|R
__device__ __half g_Ahi[(size_t)MROWS * EDIM];           // input hi
__device__ __half g_Alo[(size_t)MROWS * EDIM];           // input lo
__device__ __half g_Bh[(size_t)NCOLS * EDIM];            // [n][k] = W[k][n], fp16

// ---------------------------------------------------------------------------
// mma.sync m16n8k16 fp16 -> f32
// ---------------------------------------------------------------------------
__device__ __forceinline__ void mma16816(float* c, const uint32_t* a, const uint32_t* b) {
    asm volatile(
        "mma.sync.aligned.m16n8k16.row.col.f32.f16.f16.f32 "
        "{%0,%1,%2,%3}, {%4,%5,%6,%7}, {%8,%9}, {%0,%1,%2,%3};"
        : "+f"(c[0]), "+f"(c[1]), "+f"(c[2]), "+f"(c[3])
        : "r"(a[0]), "r"(a[1]), "r"(a[2]), "r"(a[3]), "r"(b[0]), "r"(b[1]));
}

__device__ __forceinline__ void split_half(float x, __half& h, __half& l) {
    h = __float2half_rn(x);
    l = __float2half_rn(x - __half2float(h));
}

__device__ __forceinline__ uint32_t pack2h(__half a, __half b) {
    __half2 t(a, b);   // a in low 16 bits (lower k index)
    return *(uint32_t*)&t;
}

__device__ __forceinline__ uint32_t smem_u32(const void* p) {
    uint32_t a;
    asm("{ .reg .u64 t; cvta.to.shared.u64 t, %1; cvt.u32.u64 %0, t; }" : "=r"(a) : "l"(p));
    return a;
}

__device__ __forceinline__ void cp16(uint32_t saddr, const void* gptr) {
    asm volatile("cp.async.cg.shared.global [%0], [%1], 16;" :: "r"(saddr), "l"(gptr));
}
#define CP_COMMIT() asm volatile("cp.async.commit_group;" ::: "memory")
#define CP_WAIT(N)  asm volatile("cp.async.wait_group %0;" :: "n"(N) : "memory")

// ---------------------------------------------------------------------------
// Conversion kernels
// ---------------------------------------------------------------------------
__global__ __launch_bounds__(256) void convert_A_kernel(const float* __restrict__ A) {
    size_t i = ((size_t)blockIdx.x * blockDim.x + threadIdx.x) * 4;
    if (i >= (size_t)MROWS * EDIM) return;
    float4 v = *(const float4*)&A[i];
    __half h0, l0, h1, l1, h2, l2, h3, l3;
    split_half(v.x, h0, l0); split_half(v.y, h1, l1);
    split_half(v.z, h2, l2); split_half(v.w, h3, l3);
    __half2* ph = (__half2*)&g_Ahi[i];
    __half2* pl = (__half2*)&g_Alo[i];
    ph[0] = __half2(h0, h1); ph[1] = __half2(h2, h3);
    pl[0] = __half2(l0, l1); pl[1] = __half2(l2, l3);
}

__global__ __launch_bounds__(256) void convert_W_kernel(
    const float* __restrict__ Wq, const float* __restrict__ Wk,
    const float* __restrict__ Wv, const float* __restrict__ Wr) {
    int id = blockIdx.x * blockDim.x + threadIdx.x;   // n*256 + k
    if (id >= NCOLS * EDIM) return;
    int n = id >> 8;
    int k = id & 255;
    const float* W = (n < 256) ? Wq : (n < 512) ? Wk : (n < 768) ? Wv : Wr;
    g_Bh[(size_t)n * EDIM + k] = __float2half_rn(W[(size_t)k * EDIM + (n & 255)]);
}

// ---------------------------------------------------------------------------
// Projection GEMM via mma.sync (split-fp16, 2 products), cp.async 2-stage.
// C[131072 x 1024] = A @ W.  CTA tile 128x128, warp tile 64x32, K chunks of 64.
// smem per stage: A-hi, A-lo, B tiles of 128 x 72 halves.
// ---------------------------------------------------------------------------
#define PSTR 72
#define PROJ_TILE (128 * PSTR * 2)           // 18432 B
#define PROJ_STAGE (3 * PROJ_TILE)           // 55296 B
#define PROJ_SMEM_BYTES (2 * PROJ_STAGE)     // 110592 B

__global__ __launch_bounds__(256, 2) void proj_mma_kernel() {
    extern __shared__ __half smh[];
    const uint32_t sbase = smem_u32(smh);

    const int tid = threadIdx.x;
    const int wid = tid >> 5;
    const int lane = tid & 31;
    const int m0 = blockIdx.y * 128;
    const int n0 = blockIdx.x * 128;
    const int wm = (wid & 1) * 64;
    const int wn = (wid >> 1) * 32;
    const int grp = lane >> 2;
    const int tig = lane & 3;

    float acc[4][4][4];
#pragma unroll
    for (int mf = 0; mf < 4; mf++)
#pragma unroll
        for (int nf = 0; nf < 4; nf++)
#pragma unroll
            for (int r = 0; r < 4; r++) acc[mf][nf][r] = 0.f;

    // async fill of chunk c into stage st
    auto fill = [&](int c, int st) {
        const int k0 = c * 64;
        const uint32_t sa = sbase + st * PROJ_STAGE;
#pragma unroll
        for (int it = 0; it < 4; it++) {
            int idx = tid + it * 256;          // 0..1023
            int r = idx >> 3;
            int c16 = idx & 7;
            uint32_t off = (uint32_t)(r * PSTR + c16 * 8) * 2;
            size_t ga = (size_t)(m0 + r) * EDIM + k0 + c16 * 8;
            size_t gb = (size_t)(n0 + r) * EDIM + k0 + c16 * 8;
            cp16(sa + off, g_Ahi + ga);
            cp16(sa + PROJ_TILE + off, g_Alo + ga);
            cp16(sa + 2 * PROJ_TILE + off, g_Bh + gb);
        }
    };

    fill(0, 0); CP_COMMIT();
    fill(1, 1); CP_COMMIT();

    for (int c = 0; c < 4; c++) {
        if (c < 3) { CP_WAIT(1); } else { CP_WAIT(0); }
        __syncthreads();

        const int st = c & 1;
        const __half* sAh = smh + st * (PROJ_STAGE / 2);
        const __half* sAl = sAh + PROJ_TILE / 2;
        const __half* sB  = sAh + 2 * (PROJ_TILE / 2);

#pragma unroll
        for (int kk = 0; kk < 4; kk++) {
            const int kb = kk * 16 + tig * 2;
            uint32_t bh[4][2];
#pragma unroll
            for (int nf = 0; nf < 4; nf++) {
                int n = wn + nf * 8 + grp;
                bh[nf][0] = *(const uint32_t*)&sB[n * PSTR + kb];
                bh[nf][1] = *(const uint32_t*)&sB[n * PSTR + kb + 8];
            }
#pragma unroll
            for (int mf = 0; mf < 4; mf++) {
                int m = wm + mf * 16 + grp;
                uint32_t ah[4], al[4];
                ah[0] = *(const uint32_t*)&sAh[m * PSTR + kb];
                ah[1] = *(const uint32_t*)&sAh[(m + 8) * PSTR + kb];
                ah[2] = *(const uint32_t*)&sAh[m * PSTR + kb + 8];
                ah[3] = *(const uint32_t*)&sAh[(m + 8) * PSTR + kb + 8];
                al[0] = *(const uint32_t*)&sAl[m * PSTR + kb];
                al[1] = *(const uint32_t*)&sAl[(m + 8) * PSTR + kb];
                al[2] = *(const uint32_t*)&sAl[m * PSTR + kb + 8];
                al[3] = *(const uint32_t*)&sAl[(m + 8) * PSTR + kb + 8];
#pragma unroll
                for (int nf = 0; nf < 4; nf++) {
                    mma16816(acc[mf][nf], ah, bh[nf]);
                    mma16816(acc[mf][nf], al, bh[nf]);
                }
            }
        }
        __syncthreads();
        if (c + 2 < 4) { fill(c + 2, st); CP_COMMIT(); }
    }

#pragma unroll
    for (int mf = 0; mf < 4; mf++) {
        int m = m0 + wm + mf * 16 + grp;
#pragma unroll
        for (int nf = 0; nf < 4; nf++) {
            int n = n0 + wn + nf * 8 + tig * 2;
            *(float2*)&g_qkvr[(size_t)m * NCOLS + n] = make_float2(acc[mf][nf][0], acc[mf][nf][1]);
            *(float2*)&g_qkvr[(size_t)(m + 8) * NCOLS + n] = make_float2(acc[mf][nf][2], acc[mf][nf][3]);
        }
    }
}

// ---------------------------------------------------------------------------
// Attention, register-resident S/P, split-fp16 2-product.
// One CTA per (b,h), 8 warps; warp owns 16 complete rows.
//   S = (Qh+Ql) Kh^T   (2 MMA products; K kept hi-only)
//   softmax in registers (quad shuffles), P packed to A-frags in registers
//   O = (Ph+Pl) Vh     (V^T hi-only in smem)
// Smem: Qh, Ql, Kh (128x32 @ stride 40), V^T hi (32x128 @ stride 136).
// ---------------------------------------------------------------------------
#define QKSTR 40
#define VTSTR 136
#define AOFF_QH  0
#define AOFF_QL  (AOFF_QH + 128 * QKSTR * 2)     // 10240
#define AOFF_KH  (AOFF_QL + 128 * QKSTR * 2)     // 20480
#define AOFF_VTH (AOFF_KH + 128 * QKSTR * 2)     // 30720
#define ATT_SMEM_BYTES (AOFF_VTH + 32 * VTSTR * 2)  // 39424

__global__ __launch_bounds__(256, 2) void attn_mma_kernel(float* __restrict__ out)
{
    extern __shared__ char asm_[];
    __half* sQh  = (__half*)(asm_ + AOFF_QH);
    __half* sQl  = (__half*)(asm_ + AOFF_QL);
    __half* sKh  = (__half*)(asm_ + AOFF_KH);
    __half* sVth = (__half*)(asm_ + AOFF_VTH);

    const int bh = blockIdx.x;
    const int b = bh >> 3;
    const int h = bh & 7;
    const int tid = threadIdx.x;
    const int wid = tid >> 5;
    const int lane = tid & 31;
    const int grp = lane >> 2;
    const int tig = lane & 3;

    const size_t rowbase = (size_t)(b * FDIM) * NCOLS;
    const int colQ = h * DHEAD;

    // ---- load Q,K,V (fp32) -> fp16 smem tiles; Q split, V transposed ----
#pragma unroll
    for (int s = 0; s < 4; s++) {
        int idx = tid + s * 256;               // 0..1023
        int r = idx >> 3;                      // 0..127
        int c4 = (idx & 7) * 4;                // 0..28
        const float* src = &g_qkvr[rowbase + (size_t)r * NCOLS + colQ + c4];
        float4 q = *(const float4*)(src);
        float4 k = *(const float4*)(src + 256);
        float4 v = *(const float4*)(src + 512);
        __half h0, l0, h1, l1, h2, l2, h3, l3;
        split_half(q.x, h0, l0); split_half(q.y, h1, l1);
        split_half(q.z, h2, l2); split_half(q.w, h3, l3);
        *(__half2*)&sQh[r * QKSTR + c4]     = __half2(h0, h1);
        *(__half2*)&sQh[r * QKSTR + c4 + 2] = __half2(h2, h3);
        *(__half2*)&sQl[r * QKSTR + c4]     = __half2(l0, l1);
        *(__half2*)&sQl[r * QKSTR + c4 + 2] = __half2(l2, l3);
        *(__half2*)&sKh[r * QKSTR + c4]     = __half2(__float2half_rn(k.x), __float2half_rn(k.y));
        *(__half2*)&sKh[r * QKSTR + c4 + 2] = __half2(__float2half_rn(k.z), __float2half_rn(k.w));
        sVth[(c4 + 0) * VTSTR + r] = __float2half_rn(v.x);
        sVth[(c4 + 1) * VTSTR + r] = __float2half_rn(v.y);
        sVth[(c4 + 2) * VTSTR + r] = __float2half_rn(v.z);
        sVth[(c4 + 3) * VTSTR + r] = __float2half_rn(v.w);
    }
    __syncthreads();

    // ---- S = Q K^T : warp wid handles rows wm..wm+15, all 128 cols ----
    const int wm = wid * 16;
    float acc[16][4];
#pragma unroll
    for (int nf = 0; nf < 16; nf++)
#pragma unroll
        for (int r = 0; r < 4; r++) acc[nf][r] = 0.f;

#pragma unroll
    for (int kk = 0; kk < 2; kk++) {
        const int kb = kk * 16 + tig * 2;
        const int m = wm + grp;
        uint32_t ah[4], al[4];
        ah[0] = *(const uint32_t*)&sQh[m * QKSTR + kb];
        ah[1] = *(const uint32_t*)&sQh[(m + 8) * QKSTR + kb];
        ah[2] = *(const uint32_t*)&sQh[m * QKSTR + kb + 8];
        ah[3] = *(const uint32_t*)&sQh[(m + 8) * QKSTR + kb + 8];
        al[0] = *(const uint32_t*)&sQl[m * QKSTR + kb];
        al[1] = *(const uint32_t*)&sQl[(m + 8) * QKSTR + kb];
        al[2] = *(const uint32_t*)&sQl[m * QKSTR + kb + 8];
        al[3] = *(const uint32_t*)&sQl[(m + 8) * QKSTR + kb + 8];
#pragma unroll
        for (int nf = 0; nf < 16; nf++) {
            int n = nf * 8 + grp;
            uint32_t bhf[2];
            bhf[0] = *(const uint32_t*)&sKh[n * QKSTR + kb];
            bhf[1] = *(const uint32_t*)&sKh[n * QKSTR + kb + 8];
            mma16816(acc[nf], ah, bhf);
            mma16816(acc[nf], al, bhf);
        }
    }

    // ---- softmax in registers ----
    float mx0 = -1e30f, mx1 = -1e30f;
#pragma unroll
    for (int nf = 0; nf < 16; nf++) {
        mx0 = fmaxf(mx0, fmaxf(acc[nf][0], acc[nf][1]));
        mx1 = fmaxf(mx1, fmaxf(acc[nf][2], acc[nf][3]));
    }
#pragma unroll
    for (int o = 2; o >= 1; o >>= 1) {
        mx0 = fmaxf(mx0, __shfl_xor_sync(0xffffffffu, mx0, o));
        mx1 = fmaxf(mx1, __shfl_xor_sync(0xffffffffu, mx1, o));
    }
    float s0 = 0.f, s1 = 0.f;
#pragma unroll
    for (int nf = 0; nf < 16; nf++) {
        acc[nf][0] = __expf(acc[nf][0] - mx0);
        acc[nf][1] = __expf(acc[nf][1] - mx0);
        acc[nf][2] = __expf(acc[nf][2] - mx1);
        acc[nf][3] = __expf(acc[nf][3] - mx1);
        s0 += acc[nf][0] + acc[nf][1];
        s1 += acc[nf][2] + acc[nf][3];
    }
#pragma unroll
    for (int o = 2; o >= 1; o >>= 1) {
        s0 += __shfl_xor_sync(0xffffffffu, s0, o);
        s1 += __shfl_xor_sync(0xffffffffu, s1, o);
    }
    const float inv0 = 1.0f / s0;
    const float inv1 = 1.0f / s1;

    // ---- pack P into A-fragments (hi/lo), consuming acc ----
    uint32_t ph[8][4], pl[8][4];
#pragma unroll
    for (int j = 0; j < 8; j++) {
        float p00 = acc[2 * j][0] * inv0,     p01 = acc[2 * j][1] * inv0;
        float p02 = acc[2 * j][2] * inv1,     p03 = acc[2 * j][3] * inv1;
        float p10 = acc[2 * j + 1][0] * inv0, p11 = acc[2 * j + 1][1] * inv0;
        float p12 = acc[2 * j + 1][2] * inv1, p13 = acc[2 * j + 1][3] * inv1;
        __half ha, la, hb, lb;
        split_half(p00, ha, la); split_half(p01, hb, lb);
        ph[j][0] = pack2h(ha, hb); pl[j][0] = pack2h(la, lb);
        split_half(p02, ha, la); split_half(p03, hb, lb);
        ph[j][1] = pack2h(ha, hb); pl[j][1] = pack2h(la, lb);
        split_half(p10, ha, la); split_half(p11, hb, lb);
        ph[j][2] = pack2h(ha, hb); pl[j][2] = pack2h(la, lb);
        split_half(p12, ha, la); split_half(p13, hb, lb);
        ph[j][3] = pack2h(ha, hb); pl[j][3] = pack2h(la, lb);
    }

    // ---- O = P V : warp tile m16 x n32, k=128 (8 k16 blocks) ----
    float o[4][4];
#pragma unroll
    for (int nf = 0; nf < 4; nf++)
#pragma unroll
        for (int r = 0; r < 4; r++) o[nf][r] = 0.f;

#pragma unroll
    for (int kk = 0; kk < 8; kk++) {
        const int kb = kk * 16 + tig * 2;
#pragma unroll
        for (int nf = 0; nf < 4; nf++) {
            int n = nf * 8 + grp;
            uint32_t bhf[2];
            bhf[0] = *(const uint32_t*)&sVth[n * VTSTR + kb];
            bhf[1] = *(const uint32_t*)&sVth[n * VTSTR + kb + 8];
            mma16816(o[nf], ph[kk], bhf);
            mma16816(o[nf], pl[kk], bhf);
        }
    }

    // ---- epilogue: + residual, ReLU, store ----
    const size_t orowbase = (size_t)(b * FDIM);
#pragma unroll
    for (int nf = 0; nf < 4; nf++) {
        int cc = nf * 8 + tig * 2;
        int r0 = wm + grp;
        int r1 = r0 + 8;
        float2 rr0 = *(const float2*)&g_qkvr[rowbase + (size_t)r0 * NCOLS + 768 + colQ + cc];
        float2 rr1 = *(const float2*)&g_qkvr[rowbase + (size_t)r1 * NCOLS + 768 + colQ + cc];
        float2 o0, o1;
        o0.x = fmaxf(o[nf][0] + rr0.x, 0.f);
        o0.y = fmaxf(o[nf][1] + rr0.y, 0.f);
        o1.x = fmaxf(o[nf][2] + rr1.x, 0.f);
        o1.y = fmaxf(o[nf][3] + rr1.y, 0.f);
        *(float2*)&out[(orowbase + r0) * EDIM + colQ + cc] = o0;
        *(float2*)&out[(orowbase + r1) * EDIM + colQ + cc] = o1;
    }
}

// ---------------------------------------------------------------------------
// Launch
// ---------------------------------------------------------------------------
extern "C" void kernel_launch(void* const* d_in, const int* in_sizes, int n_in,
                              void* d_out, int out_size)
{
    const float* inputs = (const float*)d_in[0];
    const float* Wq     = (const float*)d_in[1];
    const float* Wk     = (const float*)d_in[2];
    const float* Wv     = (const float*)d_in[3];
    const float* Wr     = (const float*)d_in[4];
    float* out = (float*)d_out;

    cudaFuncSetAttribute(proj_mma_kernel, cudaFuncAttributeMaxDynamicSharedMemorySize,
                         PROJ_SMEM_BYTES);
    cudaFuncSetAttribute(attn_mma_kernel, cudaFuncAttributeMaxDynamicSharedMemorySize,
                         ATT_SMEM_BYTES);

    convert_A_kernel<<<(MROWS * EDIM / 4 + 255) / 256, 256>>>(inputs);
    convert_W_kernel<<<(NCOLS * EDIM + 255) / 256, 256>>>(Wq, Wk, Wv, Wr);

    dim3 gridP(NCOLS / 128, MROWS / 128);   // 8 x 1024
    proj_mma_kernel<<<gridP, 256, PROJ_SMEM_BYTES>>>();

    attn_mma_kernel<<<BATCH * HEADS, 256, ATT_SMEM_BYTES>>>(out);
}